// round 12
// baseline (speedup 1.0000x reference)
#include <cuda_runtime.h>
#include <cuda_bf16.h>
#include <mma.h>
#include <cstdint>

using namespace nvcuda;

// Tropical (max-plus) Gram matrix via log-sum-exp GEMM on HMMA (wmma bf16).
// H[i,j] = m_i + m_j + log( sum_k e^{L(|W_ik|-m_i)} e^{L(|W_jk|-m_j)} ) / L
// R12 vs R11: finish kernel fused into the GEMM via split-K ticketing.
// ky=0 stores raw partials to g_P + release-flag; ky=1 spins, loads the
// partner partial into an accumulator fragment, adds (commutative, exact),
// applies log elementwise, then does mi+mj + H write + transposed mirror
// in-CTA (smem scratch reuses the pipeline buffers). Deadlock-free: ky=0
// blocks precede ky=1 in linear schedule order; 272 CTAs co-resident anyway.

constexpr int N_DIM = 2048;
constexpr int K_DIM = 10000;
constexpr int KHALF_PAD = 5056;                // 79 * 64
constexpr int K_PAD = 2 * KHALF_PAD;           // 10112
constexpr float LMB = 2600.0f;
constexpr int NTILES = 16;
constexpr int NPAIRS = 136;
constexpr int KTS  = 64;                       // k per pipeline stage
constexpr int NSTG = KHALF_PAD / KTS;          // 79
constexpr int ESTR = 72;                       // smem row stride (bf16) = 144B
constexpr int STAGE_BYTES = 128 * ESTR * 2;    // 18432 per operand
constexpr int NBUF = 3;
constexpr int PIPE_BYTES = NBUF * 2 * STAGE_BYTES;   // 110592 (> scratch 67584)
constexpr int NTHR = 256;
constexpr int LDC = 132;                       // epilogue scratch stride (floats)

__device__ __nv_bfloat16 g_E[(size_t)N_DIM * K_PAD];
__device__ float g_m[N_DIM];
__device__ float g_P[(size_t)N_DIM * N_DIM];   // partial sums from ky=0
__device__ int   g_flag[NPAIRS];

__device__ __forceinline__ uint32_t smem_u32(const void* p) {
    uint32_t a;
    asm("{ .reg .u64 t; cvta.to.shared.u64 t, %1; cvt.u32.u64 %0, t; }" : "=r"(a) : "l"(p));
    return a;
}
__device__ __forceinline__ void cp16(uint32_t dst, const void* src) {
    asm volatile("cp.async.cg.shared.global [%0], [%1], 16;" :: "r"(dst), "l"(src) : "memory");
}
__device__ __forceinline__ void cp_commit() {
    asm volatile("cp.async.commit_group;" ::: "memory");
}
template <int N>
__device__ __forceinline__ void cp_wait() {
    asm volatile("cp.async.wait_group %0;" :: "n"(N) : "memory");
}

// ------- kernel 1: reg-resident rowmax + E = bf16(exp(L*(|W|-m))) -------
__global__ void prep_kernel(const float* __restrict__ W) {
    const int i = blockIdx.x;
    const int t = threadIdx.x;
    // zero split-K flags for this launch (stream-ordered before GEMM)
    if (t == 0 && i < NPAIRS) g_flag[i] = 0;

    const float4* row4 = (const float4*)(W + (size_t)i * K_DIM);
    float4 v[10];
    float m = 0.0f;
#pragma unroll
    for (int q = 0; q < 10; ++q) {
        int c = t + 256 * q;
        if (c < K_DIM / 4) {
            v[q] = row4[c];
            m = fmaxf(m, fmaxf(fmaxf(fabsf(v[q].x), fabsf(v[q].y)),
                               fmaxf(fabsf(v[q].z), fabsf(v[q].w))));
        }
    }
#pragma unroll
    for (int o = 16; o; o >>= 1) m = fmaxf(m, __shfl_xor_sync(~0u, m, o));
    __shared__ float red[8];
    __shared__ float mbc;
    if ((t & 31) == 0) red[t >> 5] = m;
    __syncthreads();
    if (t < 8) {
        float w = red[t];
#pragma unroll
        for (int o = 4; o; o >>= 1) w = fmaxf(w, __shfl_xor_sync(0xffu, w, o));
        if (t == 0) { mbc = w; g_m[i] = w; }
    }
    __syncthreads();
    const float mv = mbc;

    __nv_bfloat16* erow = g_E + (size_t)i * K_PAD;
#pragma unroll
    for (int q = 0; q < 10; ++q) {
        int c = t + 256 * q;
        if (c < K_DIM / 4) {
            __nv_bfloat16 o[4];
            o[0] = __float2bfloat16(__expf((fabsf(v[q].x) - mv) * LMB));
            o[1] = __float2bfloat16(__expf((fabsf(v[q].y) - mv) * LMB));
            o[2] = __float2bfloat16(__expf((fabsf(v[q].z) - mv) * LMB));
            o[3] = __float2bfloat16(__expf((fabsf(v[q].w) - mv) * LMB));
            *(uint2*)(erow + c * 4) = *(const uint2*)o;
        }
    }
    if (t < 56) *(uint32_t*)(erow + K_DIM + 2 * t) = 0u;   // zero pad
}

// ------- kernel 2: wmma bf16 GEMM + fused split-K combine/log epilogue -------
__global__ void __launch_bounds__(NTHR, 2)
lse_gemm_kernel(float* __restrict__ H)
{
    extern __shared__ char smem[];
    const uint32_t sb = smem_u32(smem);
    const int tid = (int)threadIdx.x;
    const int wid = tid >> 5;

    int rem = (int)blockIdx.x;
    int ti = 0;
    while (rem >= NTILES - ti) { rem -= NTILES - ti; ++ti; }
    const int tj = ti + rem;
    const int gi = ti * 128, gj = tj * 128;
    const int ky = (int)blockIdx.y;
    const int bx = (int)blockIdx.x;
    const size_t kbase = (size_t)ky * KHALF_PAD;

    __shared__ float mi_s[128], mj_s[128];

    // warp grid 4(m) x 2(n): each warp 32(m) x 64(n)
    const int m0 = (wid & 3) * 32;
    const int n0 = (wid >> 2) * 64;

    wmma::fragment<wmma::accumulator, 16, 16, 16, float> acc[2][4];
#pragma unroll
    for (int a = 0; a < 2; ++a)
#pragma unroll
        for (int b = 0; b < 4; ++b) wmma::fill_fragment(acc[a][b], 0.0f);

    auto prefetch = [&](int s) {
        const int buf = s % NBUF;
        const uint32_t abase = sb + (uint32_t)buf * 2 * STAGE_BYTES;
        const uint32_t bbase = abase + STAGE_BYTES;
#pragma unroll
        for (int q = 0; q < 8; ++q) {
            int c = tid + NTHR * q;           // 0..2047
            int isB = c >> 10;
            int cc = c & 1023;
            int row = cc >> 3, sub = cc & 7;  // 8 x 16B = 128B per row
            uint32_t dst = (isB ? bbase : abase) + (uint32_t)(row * (ESTR * 2) + sub * 16);
            const __nv_bfloat16* src =
                g_E + (size_t)((isB ? gj : gi) + row) * K_PAD + kbase + (size_t)s * KTS + sub * 8;
            cp16(dst, src);
        }
        cp_commit();
    };

    prefetch(0); prefetch(1);

    typedef wmma::fragment<wmma::matrix_a, 16, 16, 16, __nv_bfloat16, wmma::row_major> FragA;
    typedef wmma::fragment<wmma::matrix_b, 16, 16, 16, __nv_bfloat16, wmma::col_major> FragB;

#pragma unroll 1
    for (int s = 0; s < NSTG; ++s) {
        if (s >= NSTG - 1) cp_wait<0>();
        else               cp_wait<1>();
        __syncthreads();
        if (s + 2 < NSTG) prefetch(s + 2);

        const int buf = s % NBUF;
        const __nv_bfloat16* A = (const __nv_bfloat16*)(smem + buf * 2 * STAGE_BYTES);
        const __nv_bfloat16* B = (const __nv_bfloat16*)(smem + buf * 2 * STAGE_BYTES + STAGE_BYTES);

        FragA af[2][2];
        FragB bfr[2][4];
#pragma unroll
        for (int a = 0; a < 2; ++a)
            wmma::load_matrix_sync(af[0][a], A + (m0 + a * 16) * ESTR, ESTR);
#pragma unroll
        for (int b = 0; b < 4; ++b)
            wmma::load_matrix_sync(bfr[0][b], B + (n0 + b * 16) * ESTR, ESTR);

#pragma unroll
        for (int kki = 0; kki < 4; ++kki) {
            const int cb = kki & 1, nb = cb ^ 1;
            if (kki < 3) {
                const int kk = (kki + 1) * 16;
#pragma unroll
                for (int a = 0; a < 2; ++a)
                    wmma::load_matrix_sync(af[nb][a], A + (m0 + a * 16) * ESTR + kk, ESTR);
#pragma unroll
                for (int b = 0; b < 4; ++b)
                    wmma::load_matrix_sync(bfr[nb][b], B + (n0 + b * 16) * ESTR + kk, ESTR);
            }
#pragma unroll
            for (int a = 0; a < 2; ++a)
#pragma unroll
                for (int b = 0; b < 4; ++b)
                    wmma::mma_sync(acc[a][b], af[cb][a], bfr[cb][b], acc[a][b]);
        }
    }

    if (ky == 0) {
        // producer: store raw partials, release flag
#pragma unroll
        for (int a = 0; a < 2; ++a)
#pragma unroll
            for (int b = 0; b < 4; ++b)
                wmma::store_matrix_sync(g_P + (size_t)(gi + m0 + a * 16) * N_DIM + gj + n0 + b * 16,
                                        acc[a][b], N_DIM, wmma::mem_row_major);
        __threadfence();
        __syncthreads();
        if (tid == 0) atomicExch(&g_flag[bx], 1);
        return;
    }

    // consumer: wait for partner's partials
    if (tid < 128) { mi_s[tid] = g_m[gi + tid]; mj_s[tid] = g_m[gj + tid]; }
    if (tid == 0) {
        while (atomicAdd(&g_flag[bx], 0) == 0) __nanosleep(64);
        __threadfence();
    }
    __syncthreads();   // all threads past mainloop; partner data visible

    // combine + log into smem scratch (reuses pipeline smem)
    float* scratch = (float*)smem;
    const float invL = 1.0f / LMB;
#pragma unroll
    for (int a = 0; a < 2; ++a)
#pragma unroll
        for (int b = 0; b < 4; ++b) {
            wmma::fragment<wmma::accumulator, 16, 16, 16, float> pf;
            wmma::load_matrix_sync(pf, g_P + (size_t)(gi + m0 + a * 16) * N_DIM + gj + n0 + b * 16,
                                   N_DIM, wmma::mem_row_major);
#pragma unroll
            for (int e = 0; e < pf.num_elements; ++e)
                acc[a][b].x[e] = __logf(acc[a][b].x[e] + pf.x[e]) * invL;
            wmma::store_matrix_sync(scratch + (size_t)(m0 + a * 16) * LDC + (n0 + b * 16),
                                    acc[a][b], LDC, wmma::mem_row_major);
        }
    __syncthreads();

    // add mi+mj, write upper tile, keep v in scratch for mirror
#pragma unroll 4
    for (int it = 0; it < 16; ++it) {
        int idx = tid + it * 256;
        int r = idx >> 5, c4 = (idx & 31) * 4;
        float base = mi_s[r];
        float4 v;
        v.x = base + mj_s[c4 + 0] + scratch[r * LDC + c4 + 0];
        v.y = base + mj_s[c4 + 1] + scratch[r * LDC + c4 + 1];
        v.z = base + mj_s[c4 + 2] + scratch[r * LDC + c4 + 2];
        v.w = base + mj_s[c4 + 3] + scratch[r * LDC + c4 + 3];
        *(float4*)&H[(size_t)(gi + r) * N_DIM + gj + c4] = v;
        scratch[r * LDC + c4 + 0] = v.x;
        scratch[r * LDC + c4 + 1] = v.y;
        scratch[r * LDC + c4 + 2] = v.z;
        scratch[r * LDC + c4 + 3] = v.w;
    }

    if (ti == tj) return;

    __syncthreads();
    // mirror: H[gj+r][gi+c] = v[c][r] via transposed smem reads
#pragma unroll 4
    for (int it = 0; it < 16; ++it) {
        int idx = tid + it * 256;
        int r = idx >> 5, c4 = (idx & 31) * 4;
        float4 v;
        v.x = scratch[(c4 + 0) * LDC + r];
        v.y = scratch[(c4 + 1) * LDC + r];
        v.z = scratch[(c4 + 2) * LDC + r];
        v.w = scratch[(c4 + 3) * LDC + r];
        *(float4*)&H[(size_t)(gj + r) * N_DIM + gi + c4] = v;
    }
}

// ---------------- launcher ----------------
extern "C" void kernel_launch(void* const* d_in, const int* in_sizes, int n_in,
                              void* d_out, int out_size) {
    const float* W = (const float*)d_in[0];
    float* H = (float*)d_out;

    cudaFuncSetAttribute(lse_gemm_kernel, cudaFuncAttributeMaxDynamicSharedMemorySize, PIPE_BYTES);

    prep_kernel<<<N_DIM, 256>>>(W);
    dim3 gg(NPAIRS, 2);
    lse_gemm_kernel<<<gg, NTHR, PIPE_BYTES>>>(H);
}

// round 13
// speedup vs baseline: 1.0174x; 1.0174x over previous
#include <cuda_runtime.h>
#include <cuda_bf16.h>
#include <mma.h>
#include <cstdint>

using namespace nvcuda;

// Tropical (max-plus) Gram matrix via log-sum-exp GEMM on HMMA (wmma bf16).
// H[i,j] = m_i + m_j + log( sum_k e^{L(|W_ik|-m_i)} e^{L(|W_jk|-m_j)} ) / L
// R13 vs R12: symmetric split epilogue. Each K-half CTA stores its full-tile
// partial to SMEM scratch, exports the OTHER half's 64 rows to g_P with
// coalesced float4 copies (no fragment<->global ops), flags, spins on its
// partner, then combines/logs/writes its OWN 64 rows + its 64-col mirror
// slice. Diagonal tiles: both halves write full width -> no mirror needed.
// fp32 combine order unchanged (a+b commutative) -> bit-identical rel_err.

constexpr int N_DIM = 2048;
constexpr int K_DIM = 10000;
constexpr int KHALF_PAD = 5056;                // 79 * 64
constexpr int K_PAD = 2 * KHALF_PAD;           // 10112
constexpr float LMB = 2600.0f;
constexpr int NTILES = 16;
constexpr int NPAIRS = 136;
constexpr int KTS  = 64;                       // k per pipeline stage
constexpr int NSTG = KHALF_PAD / KTS;          // 79
constexpr int ESTR = 72;                       // smem row stride (bf16) = 144B
constexpr int STAGE_BYTES = 128 * ESTR * 2;    // 18432 per operand
constexpr int NBUF = 3;
constexpr int PIPE_BYTES = NBUF * 2 * STAGE_BYTES;   // 110592 (> scratch 67584)
constexpr int NTHR = 256;
constexpr int LDC = 132;                       // epilogue scratch stride (floats)

__device__ __nv_bfloat16 g_E[(size_t)N_DIM * K_PAD];
__device__ float g_m[N_DIM];
__device__ float g_P[(size_t)N_DIM * N_DIM];   // cross-exported partial sums
__device__ int   g_flag[NPAIRS * 2];

__device__ __forceinline__ uint32_t smem_u32(const void* p) {
    uint32_t a;
    asm("{ .reg .u64 t; cvta.to.shared.u64 t, %1; cvt.u32.u64 %0, t; }" : "=r"(a) : "l"(p));
    return a;
}
__device__ __forceinline__ void cp16(uint32_t dst, const void* src) {
    asm volatile("cp.async.cg.shared.global [%0], [%1], 16;" :: "r"(dst), "l"(src) : "memory");
}
__device__ __forceinline__ void cp_commit() {
    asm volatile("cp.async.commit_group;" ::: "memory");
}
template <int N>
__device__ __forceinline__ void cp_wait() {
    asm volatile("cp.async.wait_group %0;" :: "n"(N) : "memory");
}

// ------- kernel 1: reg-resident rowmax + E = bf16(exp(L*(|W|-m))) -------
__global__ void prep_kernel(const float* __restrict__ W) {
    const int i = blockIdx.x;
    const int t = threadIdx.x;
    if (t == 0 && i < NPAIRS * 2) g_flag[i] = 0;   // zero split-K flags

    const float4* row4 = (const float4*)(W + (size_t)i * K_DIM);
    float4 v[10];
    float m = 0.0f;
#pragma unroll
    for (int q = 0; q < 10; ++q) {
        int c = t + 256 * q;
        if (c < K_DIM / 4) {
            v[q] = row4[c];
            m = fmaxf(m, fmaxf(fmaxf(fabsf(v[q].x), fabsf(v[q].y)),
                               fmaxf(fabsf(v[q].z), fabsf(v[q].w))));
        }
    }
#pragma unroll
    for (int o = 16; o; o >>= 1) m = fmaxf(m, __shfl_xor_sync(~0u, m, o));
    __shared__ float red[8];
    __shared__ float mbc;
    if ((t & 31) == 0) red[t >> 5] = m;
    __syncthreads();
    if (t < 8) {
        float w = red[t];
#pragma unroll
        for (int o = 4; o; o >>= 1) w = fmaxf(w, __shfl_xor_sync(0xffu, w, o));
        if (t == 0) { mbc = w; g_m[i] = w; }
    }
    __syncthreads();
    const float mv = mbc;

    __nv_bfloat16* erow = g_E + (size_t)i * K_PAD;
#pragma unroll
    for (int q = 0; q < 10; ++q) {
        int c = t + 256 * q;
        if (c < K_DIM / 4) {
            __nv_bfloat16 o[4];
            o[0] = __float2bfloat16(__expf((fabsf(v[q].x) - mv) * LMB));
            o[1] = __float2bfloat16(__expf((fabsf(v[q].y) - mv) * LMB));
            o[2] = __float2bfloat16(__expf((fabsf(v[q].z) - mv) * LMB));
            o[3] = __float2bfloat16(__expf((fabsf(v[q].w) - mv) * LMB));
            *(uint2*)(erow + c * 4) = *(const uint2*)o;
        }
    }
    if (t < 56) *(uint32_t*)(erow + K_DIM + 2 * t) = 0u;   // zero pad
}

// ------- kernel 2: wmma bf16 GEMM + symmetric split-K epilogue -------
__global__ void __launch_bounds__(NTHR, 2)
lse_gemm_kernel(float* __restrict__ H)
{
    extern __shared__ char smem[];
    const uint32_t sb = smem_u32(smem);
    const int tid = (int)threadIdx.x;
    const int wid = tid >> 5;

    int rem = (int)blockIdx.x;
    int ti = 0;
    while (rem >= NTILES - ti) { rem -= NTILES - ti; ++ti; }
    const int tj = ti + rem;
    const int gi = ti * 128, gj = tj * 128;
    const int ky = (int)blockIdx.y;
    const int bx = (int)blockIdx.x;
    const size_t kbase = (size_t)ky * KHALF_PAD;

    __shared__ float mi_s[128], mj_s[128];

    // warp grid 4(m) x 2(n): each warp 32(m) x 64(n)
    const int m0 = (wid & 3) * 32;
    const int n0 = (wid >> 2) * 64;

    wmma::fragment<wmma::accumulator, 16, 16, 16, float> acc[2][4];
#pragma unroll
    for (int a = 0; a < 2; ++a)
#pragma unroll
        for (int b = 0; b < 4; ++b) wmma::fill_fragment(acc[a][b], 0.0f);

    auto prefetch = [&](int s) {
        const int buf = s % NBUF;
        const uint32_t abase = sb + (uint32_t)buf * 2 * STAGE_BYTES;
        const uint32_t bbase = abase + STAGE_BYTES;
#pragma unroll
        for (int q = 0; q < 8; ++q) {
            int c = tid + NTHR * q;           // 0..2047
            int isB = c >> 10;
            int cc = c & 1023;
            int row = cc >> 3, sub = cc & 7;  // 8 x 16B = 128B per row
            uint32_t dst = (isB ? bbase : abase) + (uint32_t)(row * (ESTR * 2) + sub * 16);
            const __nv_bfloat16* src =
                g_E + (size_t)((isB ? gj : gi) + row) * K_PAD + kbase + (size_t)s * KTS + sub * 8;
            cp16(dst, src);
        }
        cp_commit();
    };

    prefetch(0); prefetch(1);

    typedef wmma::fragment<wmma::matrix_a, 16, 16, 16, __nv_bfloat16, wmma::row_major> FragA;
    typedef wmma::fragment<wmma::matrix_b, 16, 16, 16, __nv_bfloat16, wmma::col_major> FragB;

#pragma unroll 1
    for (int s = 0; s < NSTG; ++s) {
        if (s >= NSTG - 1) cp_wait<0>();
        else               cp_wait<1>();
        __syncthreads();
        if (s + 2 < NSTG) prefetch(s + 2);

        const int buf = s % NBUF;
        const __nv_bfloat16* A = (const __nv_bfloat16*)(smem + buf * 2 * STAGE_BYTES);
        const __nv_bfloat16* B = (const __nv_bfloat16*)(smem + buf * 2 * STAGE_BYTES + STAGE_BYTES);

        FragA af[2][2];
        FragB bfr[2][4];
#pragma unroll
        for (int a = 0; a < 2; ++a)
            wmma::load_matrix_sync(af[0][a], A + (m0 + a * 16) * ESTR, ESTR);
#pragma unroll
        for (int b = 0; b < 4; ++b)
            wmma::load_matrix_sync(bfr[0][b], B + (n0 + b * 16) * ESTR, ESTR);

#pragma unroll
        for (int kki = 0; kki < 4; ++kki) {
            const int cb = kki & 1, nb = cb ^ 1;
            if (kki < 3) {
                const int kk = (kki + 1) * 16;
#pragma unroll
                for (int a = 0; a < 2; ++a)
                    wmma::load_matrix_sync(af[nb][a], A + (m0 + a * 16) * ESTR + kk, ESTR);
#pragma unroll
                for (int b = 0; b < 4; ++b)
                    wmma::load_matrix_sync(bfr[nb][b], B + (n0 + b * 16) * ESTR + kk, ESTR);
            }
#pragma unroll
            for (int a = 0; a < 2; ++a)
#pragma unroll
                for (int b = 0; b < 4; ++b)
                    wmma::mma_sync(acc[a][b], af[cb][a], bfr[cb][b], acc[a][b]);
        }
    }
    __syncthreads();   // mainloop done; safe to reuse pipeline smem as scratch

    // ---- symmetric split epilogue ----
    float* scratch = (float*)smem;
    const int own0   = 64 * ky;        // rows this CTA finalizes
    const int other0 = 64 - own0;      // rows this CTA exports

    // 1) all warps dump acc into full-tile smem scratch (fast path)
#pragma unroll
    for (int a = 0; a < 2; ++a)
#pragma unroll
        for (int b = 0; b < 4; ++b)
            wmma::store_matrix_sync(scratch + (size_t)(m0 + a * 16) * LDC + (n0 + b * 16),
                                    acc[a][b], LDC, wmma::mem_row_major);
    if (tid < 128) { mi_s[tid] = g_m[gi + tid]; mj_s[tid] = g_m[gj + tid]; }
    __syncthreads();

    // 2) export other half's rows to g_P, coalesced float4 (2048 f4 / 256 thr)
#pragma unroll
    for (int q = 0; q < 8; ++q) {
        int idx = tid + 256 * q;
        int rr = idx >> 5, c4 = (idx & 31) * 4;
        float4 v = *(float4*)&scratch[(other0 + rr) * LDC + c4];
        *(float4*)&g_P[(size_t)(gi + other0 + rr) * N_DIM + gj + c4] = v;
    }
    __threadfence();
    __syncthreads();
    if (tid == 0) {
        atomicExch(&g_flag[2 * bx + ky], 1);
        while (atomicAdd(&g_flag[2 * bx + (1 - ky)], 0) == 0) __nanosleep(64);
        __threadfence();
    }
    __syncthreads();

    // 3) combine own rows: log(own_scratch + partner_gP), write H, keep for mirror
    const float invL = 1.0f / LMB;
#pragma unroll
    for (int q = 0; q < 8; ++q) {
        int idx = tid + 256 * q;
        int rr = idx >> 5, c4 = (idx & 31) * 4;
        int r = own0 + rr;
        float* srow = &scratch[r * LDC + c4];
        float4 p0 = *(float4*)srow;
        float4 p1 = *(const float4*)&g_P[(size_t)(gi + r) * N_DIM + gj + c4];
        float base = mi_s[r];
        float4 v;
        v.x = base + mj_s[c4 + 0] + __logf(p0.x + p1.x) * invL;
        v.y = base + mj_s[c4 + 1] + __logf(p0.y + p1.y) * invL;
        v.z = base + mj_s[c4 + 2] + __logf(p0.z + p1.z) * invL;
        v.w = base + mj_s[c4 + 3] + __logf(p0.w + p1.w) * invL;
        *(float4*)&H[(size_t)(gi + r) * N_DIM + gj + c4] = v;
        srow[0] = v.x; srow[1] = v.y; srow[2] = v.z; srow[3] = v.w;
    }

    if (ti == tj) return;   // diagonal: both halves wrote full width; no mirror

    __syncthreads();
    // 4) mirror own 64-column slice: H[gj+c][gi+own0+rr] = v[own0+rr][c]
#pragma unroll
    for (int q = 0; q < 8; ++q) {
        int idx = tid + 256 * q;
        int c  = idx >> 4;                 // 0..127
        int r4 = (idx & 15) * 4;           // 0..60
        float4 v;
        v.x = scratch[(own0 + r4 + 0) * LDC + c];
        v.y = scratch[(own0 + r4 + 1) * LDC + c];
        v.z = scratch[(own0 + r4 + 2) * LDC + c];
        v.w = scratch[(own0 + r4 + 3) * LDC + c];
        *(float4*)&H[(size_t)(gj + c) * N_DIM + gi + own0 + r4] = v;
    }
}

// ---------------- launcher ----------------
extern "C" void kernel_launch(void* const* d_in, const int* in_sizes, int n_in,
                              void* d_out, int out_size) {
    const float* W = (const float*)d_in[0];
    float* H = (float*)d_out;

    cudaFuncSetAttribute(lse_gemm_kernel, cudaFuncAttributeMaxDynamicSharedMemorySize, PIPE_BYTES);

    prep_kernel<<<N_DIM, 256>>>(W);
    dim3 gg(NPAIRS, 2);
    lse_gemm_kernel<<<gg, NTHR, PIPE_BYTES>>>(H);
}